// round 2
// baseline (speedup 1.0000x reference)
#include <cuda_runtime.h>
#include <math.h>

// ---------------------------------------------------------------------------
// CLIP_SVPR_ReID fused head, restructured:
//   - single-query cross attention folded to qhat/ctx form (no K/V materialization)
//   - router collapsed to a scalar score
//   - MoE expert GEMM (dominant cost) as a 128x128 fp32 tiled GEMM
// kernel_launch contains ONLY kernel launches (no runtime API calls at all):
// scratch lives in a __device__ global, addressed in-kernel by offset.
// ---------------------------------------------------------------------------

namespace {
constexpr int Bx = 256;   // batch
constexpr int Nx = 256;   // patches
constexpr int Cx = 768;   // channels
constexpr int Ax = 10;    // attributes
constexpr int Hx = 8;     // heads
constexpr int Ex = 4;     // experts
constexpr int Dx = 96;    // head dim
constexpr float SCALE = 0.1020620726159657f; // 96^-0.5

constexpr long OFF_Q     = 0;                                 // [B,C]
constexpr long OFF_QHAT  = OFF_Q     + (long)Bx * Cx;         // [B,H,C]
constexpr long OFF_CTX   = OFF_QHAT  + (long)Bx * Hx * Cx;    // [B,H,C]
constexpr long OFF_O     = OFF_CTX   + (long)Bx * Hx * Cx;    // [B,C]
constexpr long OFF_MOEIN = OFF_O     + (long)Bx * Cx;         // [B,C]
constexpr long OFF_ATTR  = OFF_MOEIN + (long)Bx * Cx;         // [B*A,C]
constexpr long OFF_GATEW = OFF_ATTR  + (long)Bx * Ax * Cx;    // [B*A,E]
constexpr long OFF_SCORE = OFF_GATEW + (long)Bx * Ax * Ex;    // [B*A]
constexpr long OFF_EO    = OFF_SCORE + (long)Bx * Ax;         // [B*A, E*C]
constexpr long SCRATCH_TOTAL = OFF_EO + (long)Bx * Ax * Ex * Cx;
} // namespace

__device__ float g_scratch[SCRATCH_TOTAL];

// Resolve an operand: real input pointer, or offset into g_scratch.
__device__ __forceinline__ const float* rsv(const float* p, long base) {
    return p ? p : (const float*)g_scratch + base;
}
__device__ __forceinline__ float* rsvw(float* p, long base) {
    return p ? p : (float*)g_scratch + base;
}

// ---------------------------------------------------------------------------
// Generic tiled fp32 GEMM.
//   C[m,n] = sum_k A[m,k] * B'[k,n] (+ bias[n])
//   BT=true : B is [N,K] row-major (torch Linear weight, "NT")
//   BT=false: B is [K,N] row-major ("NN")
// Batched via blockIdx.z with element offsets aOff/bOff/cOff/biasOff.
// BK=16, 256 threads (16x16), TM x TN microtile per thread.
// Null pointer + base = operand lives in g_scratch at that offset.
// ---------------------------------------------------------------------------
template <int BM, int BN, int TM, int TN, bool BT>
__global__ __launch_bounds__(256) void gemm_kernel(
    const float* __restrict__ Ain, long aBase, int lda, long aOff,
    const float* __restrict__ Bin, long bBase, int ldb, long bOff,
    const float* __restrict__ biasin, long biasBase, int biasOff, int hasBias,
    float* __restrict__ Cin, long cBase, int ldc, long cOff,
    int M, int Nc, int K)
{
    constexpr int BK = 16;
    __shared__ __align__(16) float As[BK][BM];
    __shared__ __align__(16) float Bs[BK][BN];

    const float* Ap = rsv(Ain, aBase);
    const float* Bp = rsv(Bin, bBase);
    const float* biasp = hasBias ? rsv(biasin, biasBase) : nullptr;
    float* Cp = rsvw(Cin, cBase);

    const int z = blockIdx.z;
    Ap += (long)z * aOff;
    Bp += (long)z * bOff;
    Cp += (long)z * cOff;
    if (biasp) biasp += (long)z * biasOff;

    const int tid = threadIdx.x;
    const int tx = tid & 15;
    const int ty = tid >> 4;
    const int m0 = blockIdx.y * BM;
    const int n0 = blockIdx.x * BN;

    float acc[TM][TN];
#pragma unroll
    for (int i = 0; i < TM; i++)
#pragma unroll
        for (int j = 0; j < TN; j++) acc[i][j] = 0.f;

    for (int k0 = 0; k0 < K; k0 += BK) {
        // A tile: BM rows x 16 k, transposed into As[k][m]
#pragma unroll
        for (int i = 0; i < BM / 64; i++) {
            int idx = tid + i * 256;     // BM*4 float4 slots
            int r = idx >> 2;
            int kq = (idx & 3) << 2;
            float4 v = make_float4(0.f, 0.f, 0.f, 0.f);
            if (m0 + r < M)
                v = *reinterpret_cast<const float4*>(Ap + (long)(m0 + r) * lda + k0 + kq);
            As[kq + 0][r] = v.x; As[kq + 1][r] = v.y;
            As[kq + 2][r] = v.z; As[kq + 3][r] = v.w;
        }
        if (BT) {
#pragma unroll
            for (int i = 0; i < BN / 64; i++) {
                int idx = tid + i * 256;  // BN*4 float4 slots
                int r = idx >> 2;
                int kq = (idx & 3) << 2;
                float4 v = make_float4(0.f, 0.f, 0.f, 0.f);
                if (n0 + r < Nc)
                    v = *reinterpret_cast<const float4*>(Bp + (long)(n0 + r) * ldb + k0 + kq);
                Bs[kq + 0][r] = v.x; Bs[kq + 1][r] = v.y;
                Bs[kq + 2][r] = v.z; Bs[kq + 3][r] = v.w;
            }
        } else {
#pragma unroll
            for (int i = 0; i < BN / 64; i++) {
                int idx = tid + i * 256;  // 16*BN/4 float4 slots
                int r = idx / (BN / 4);
                int cq = (idx % (BN / 4)) << 2;
                float4 v = make_float4(0.f, 0.f, 0.f, 0.f);
                if (n0 + cq < Nc)
                    v = *reinterpret_cast<const float4*>(Bp + (long)(k0 + r) * ldb + n0 + cq);
                *reinterpret_cast<float4*>(&Bs[r][cq]) = v;
            }
        }
        __syncthreads();
#pragma unroll
        for (int kk = 0; kk < BK; kk++) {
            float af[TM], bf[TN];
#pragma unroll
            for (int i = 0; i < TM; i++) af[i] = As[kk][ty * TM + i];
#pragma unroll
            for (int j = 0; j < TN; j++) bf[j] = Bs[kk][tx * TN + j];
#pragma unroll
            for (int i = 0; i < TM; i++)
#pragma unroll
                for (int j = 0; j < TN; j++)
                    acc[i][j] += af[i] * bf[j];
        }
        __syncthreads();
    }

#pragma unroll
    for (int i = 0; i < TM; i++) {
        int m = m0 + ty * TM + i;
        if (m >= M) continue;
#pragma unroll
        for (int j = 0; j < TN; j++) {
            int n = n0 + tx * TN + j;
            if (n < Nc) {
                float v = acc[i][j];
                if (biasp) v += biasp[n];
                Cp[(long)m * ldc + n] = v;
            }
        }
    }
}

// ---------------------------------------------------------------------------
// Fused attention for the single query token. One CTA per batch element.
//   phase 1: logits[h,n] = SCALE * qhat[b,h,:] . x[b,n,:]
//   softmax over n per head
//   phase 2: ctx[b,h,c] = sum_n att[h,n] * x[b,n,c]
// (bk cancels in softmax; bv is applied later in the o-projection GEMM.)
// ---------------------------------------------------------------------------
__global__ __launch_bounds__(256) void attn_kernel(const float* __restrict__ x)
{
    __shared__ float qs[Hx * Cx];   // 24 KB
    __shared__ float att[Hx * Nx];  // 8 KB
    const float* qhat = (const float*)g_scratch + OFF_QHAT;
    float* ctx = (float*)g_scratch + OFF_CTX;
    const int b = blockIdx.x;
    const int t = threadIdx.x;
    const int warp = t >> 5, lane = t & 31;
    const float* xb = x + (long)b * Nx * Cx;

    for (int i = t; i < Hx * Cx; i += 256) qs[i] = qhat[(long)b * Hx * Cx + i];
    __syncthreads();

    // phase 1: each warp owns n = warp, warp+8, ...
    for (int n = warp; n < Nx; n += 8) {
        const float* xr = xb + (long)n * Cx;
        float acc[Hx];
#pragma unroll
        for (int h = 0; h < Hx; h++) acc[h] = 0.f;
        for (int c = lane; c < Cx; c += 32) {
            float xv = xr[c];
#pragma unroll
            for (int h = 0; h < Hx; h++) acc[h] += xv * qs[h * Cx + c];
        }
#pragma unroll
        for (int h = 0; h < Hx; h++) {
#pragma unroll
            for (int o = 16; o; o >>= 1)
                acc[h] += __shfl_xor_sync(0xffffffffu, acc[h], o);
        }
        if (lane == 0) {
#pragma unroll
            for (int h = 0; h < Hx; h++) att[h * Nx + n] = acc[h] * SCALE;
        }
    }
    __syncthreads();

    // softmax: warp h handles head h
    {
        const int h = warp;
        float v[Nx / 32];
        float mx = -3.4e38f;
#pragma unroll
        for (int i = 0; i < Nx / 32; i++) {
            v[i] = att[h * Nx + lane + 32 * i];
            mx = fmaxf(mx, v[i]);
        }
#pragma unroll
        for (int o = 16; o; o >>= 1)
            mx = fmaxf(mx, __shfl_xor_sync(0xffffffffu, mx, o));
        float s = 0.f;
#pragma unroll
        for (int i = 0; i < Nx / 32; i++) { v[i] = __expf(v[i] - mx); s += v[i]; }
#pragma unroll
        for (int o = 16; o; o >>= 1)
            s += __shfl_xor_sync(0xffffffffu, s, o);
        float inv = 1.f / s;
#pragma unroll
        for (int i = 0; i < Nx / 32; i++) att[h * Nx + lane + 32 * i] = v[i] * inv;
    }
    __syncthreads();

    // phase 2: thread t owns channels t, t+256, t+512 for all 8 heads
    float a0[Hx], a1[Hx], a2[Hx];
#pragma unroll
    for (int h = 0; h < Hx; h++) { a0[h] = 0.f; a1[h] = 0.f; a2[h] = 0.f; }
    for (int n = 0; n < Nx; n++) {
        const float* xr = xb + (long)n * Cx;
        float x0 = xr[t], x1 = xr[t + 256], x2 = xr[t + 512];
#pragma unroll
        for (int h = 0; h < Hx; h++) {
            float w = att[h * Nx + n];
            a0[h] += w * x0; a1[h] += w * x1; a2[h] += w * x2;
        }
    }
#pragma unroll
    for (int h = 0; h < Hx; h++) {
        float* cb = ctx + (long)b * Hx * Cx + h * Cx;
        cb[t] = a0[h]; cb[t + 256] = a1[h]; cb[t + 512] = a2[h];
    }
}

// ---------------------------------------------------------------------------
// attr_in build + gate top-3 softmax weights + router score.
// One CTA per (b, a) row.
// score = gelu_tanh(attr . r1_w + r1_b) * mean(r2_w) + mean(r2_b)
// ---------------------------------------------------------------------------
__device__ __forceinline__ float gelu_tanh(float v) {
    return 0.5f * v * (1.f + tanhf(0.7978845608028654f * (v + 0.044715f * v * v * v)));
}

__global__ __launch_bounds__(256) void attr_build_kernel(
    const float* __restrict__ prompt, const float* __restrict__ vcls,
    const float* __restrict__ gate_w, const float* __restrict__ gate_b,
    const float* __restrict__ r1_w, const float* __restrict__ r1_b,
    const float* __restrict__ r2_w, const float* __restrict__ r2_b)
{
    const float* moein = (const float*)g_scratch + OFF_MOEIN;
    float* attr  = (float*)g_scratch + OFF_ATTR;
    float* gatew = (float*)g_scratch + OFF_GATEW;
    float* scores = (float*)g_scratch + OFF_SCORE;

    const int row = blockIdx.x;
    const int b = row / Ax, a = row % Ax;
    const int t = threadIdx.x;
    float p[7] = {0, 0, 0, 0, 0, 0, 0};  // g0..g3, r1 dot, sum r2_w, sum r2_b
    for (int c = t; c < Cx; c += 256) {
        float v = moein[(long)b * Cx + c] + prompt[a * Cx + c] + vcls[(long)b * Cx + c];
        attr[(long)row * Cx + c] = v;
        p[0] += v * gate_w[0 * Cx + c];
        p[1] += v * gate_w[1 * Cx + c];
        p[2] += v * gate_w[2 * Cx + c];
        p[3] += v * gate_w[3 * Cx + c];
        p[4] += v * r1_w[c];
        p[5] += r2_w[c];
        p[6] += r2_b[c];
    }
#pragma unroll
    for (int i = 0; i < 7; i++)
#pragma unroll
        for (int o = 16; o; o >>= 1)
            p[i] += __shfl_xor_sync(0xffffffffu, p[i], o);

    __shared__ float red[8][7];
    const int warp = t >> 5, lane = t & 31;
    if (lane == 0)
        for (int i = 0; i < 7; i++) red[warp][i] = p[i];
    __syncthreads();

    if (t == 0) {
        float s[7];
        for (int i = 0; i < 7; i++) {
            s[i] = 0.f;
            for (int w = 0; w < 8; w++) s[i] += red[w][i];
        }
        float g[4];
        for (int e = 0; e < 4; e++) g[e] = s[e] + gate_b[e];
        // third-largest threshold (top-3 of 4, ties kept like jnp.where(g >= thr))
        float srt[4] = {g[0], g[1], g[2], g[3]};
        for (int i = 0; i < 3; i++)
            for (int j = 0; j < 3 - i; j++)
                if (srt[j] < srt[j + 1]) { float tm = srt[j]; srt[j] = srt[j + 1]; srt[j + 1] = tm; }
        float thr = srt[2], mx = srt[0];
        float w[4], ws = 0.f;
        for (int e = 0; e < 4; e++) {
            if (g[e] >= thr) { w[e] = __expf(g[e] - mx); ws += w[e]; }
            else w[e] = 0.f;
        }
        float inv = 1.f / ws;
        for (int e = 0; e < 4; e++) gatew[(long)row * 4 + e] = w[e] * inv;

        float hsc = gelu_tanh(s[4] + r1_b[0]);
        scores[row] = hsc * (s[5] * (1.f / 768.f)) + s[6] * (1.f / 768.f);
    }
}

// ---------------------------------------------------------------------------
// Final combine: top-7 attribute softmax weights fused with the per-(b,a)
// gate weights; out[b,c] = sum_{a,e} coef[a,e] * eo[b,a,e,c].
// One CTA per batch element.
// ---------------------------------------------------------------------------
__global__ __launch_bounds__(256) void final_kernel(float* __restrict__ out)
{
    const float* eo = (const float*)g_scratch + OFF_EO;
    const float* gatew = (const float*)g_scratch + OFF_GATEW;
    const float* scores = (const float*)g_scratch + OFF_SCORE;

    const int b = blockIdx.x, t = threadIdx.x;
    __shared__ float coef[Ax * Ex];
    __shared__ float sc[Ax];
    if (t < Ax) sc[t] = scores[b * Ax + t];
    __syncthreads();
    if (t == 0) {
        float mx = sc[0];
        for (int a = 1; a < Ax; a++) mx = fmaxf(mx, sc[a]);
        float wt[Ax];
        float ssum = 0.f;
        for (int a = 0; a < Ax; a++) {
            int rank = 0;
            for (int a2 = 0; a2 < Ax; a2++)
                if (sc[a2] > sc[a] || (sc[a2] == sc[a] && a2 < a)) rank++;
            if (rank < 7) { wt[a] = __expf(sc[a] - mx); ssum += wt[a]; }
            else wt[a] = 0.f;
        }
        float inv = 1.f / ssum;
        for (int a = 0; a < Ax; a++) {
            float w = wt[a] * inv;
            for (int e = 0; e < Ex; e++)
                coef[a * Ex + e] = w * gatew[(long)(b * Ax + a) * Ex + e];
        }
    }
    __syncthreads();
    float cf[Ax * Ex];
#pragma unroll
    for (int i = 0; i < Ax * Ex; i++) cf[i] = coef[i];
    const float* eb = eo + (long)b * Ax * Ex * Cx;
    for (int c = t; c < Cx; c += 256) {
        float acc = 0.f;
#pragma unroll
        for (int a = 0; a < Ax; a++)
#pragma unroll
            for (int e = 0; e < Ex; e++)
                acc += cf[a * Ex + e] * eb[(long)a * Ex * Cx + e * Cx + c];
        out[(long)b * Cx + c] = acc;
    }
}

// ---------------------------------------------------------------------------
// Launcher — kernel launches ONLY, no runtime API calls of any kind.
// ---------------------------------------------------------------------------
extern "C" void kernel_launch(void* const* d_in, const int* in_sizes, int n_in,
                              void* d_out, int out_size)
{
    (void)in_sizes; (void)n_in; (void)out_size;
    const float* text_cls   = (const float*)d_in[0];
    const float* visual_cls = (const float*)d_in[1];
    const float* x          = (const float*)d_in[2];  // visual_patchs
    const float* prompt     = (const float*)d_in[3];
    const float* Wq  = (const float*)d_in[4];
    const float* bq  = (const float*)d_in[5];
    const float* Wk  = (const float*)d_in[6];
    // d_in[7] = bk: cancels in softmax, unused
    const float* Wv  = (const float*)d_in[8];
    const float* bv  = (const float*)d_in[9];
    const float* Wo  = (const float*)d_in[10];
    const float* bo  = (const float*)d_in[11];
    const float* gate_w = (const float*)d_in[12];
    const float* gate_b = (const float*)d_in[13];
    const float* exp_w  = (const float*)d_in[14];
    const float* exp_b  = (const float*)d_in[15];
    const float* r1_w   = (const float*)d_in[16];
    const float* r1_b   = (const float*)d_in[17];
    const float* r2_w   = (const float*)d_in[18];
    const float* r2_b   = (const float*)d_in[19];
    float* out = (float*)d_out;

    // 1) q = text_cls @ Wq^T + bq                      [256,768]
    gemm_kernel<64, 64, 4, 4, true><<<dim3(12, 4, 1), 256>>>(
        text_cls, 0, Cx, 0,  Wq, 0, Cx, 0,  bq, 0, 0, 1,
        nullptr, OFF_Q, Cx, 0,  Bx, Cx, Cx);

    // 2) qhat[b,h,:] = q[b,h-slice] @ Wk[h-rows]       NN, batched over H
    gemm_kernel<64, 64, 4, 4, false><<<dim3(12, 4, Hx), 256>>>(
        nullptr, OFF_Q, Cx, (long)Dx,  Wk, 0, Cx, (long)Dx * Cx,  nullptr, 0, 0, 0,
        nullptr, OFF_QHAT, Hx * Cx, (long)Cx,  Bx, Cx, Dx);

    // 3) fused logits + softmax + ctx                  one CTA per b
    attn_kernel<<<Bx, 256>>>(x);

    // 4) o[b, h*96+dd] = ctx[b,h] @ Wv_h^T + bv        NT, batched over H
    gemm_kernel<64, 64, 4, 4, true><<<dim3(2, 4, Hx), 256>>>(
        nullptr, OFF_CTX, Hx * Cx, (long)Cx,  Wv, 0, Cx, (long)Dx * Cx,  bv, 0, Dx, 1,
        nullptr, OFF_O, Cx, (long)Dx,  Bx, Dx, Cx);

    // 5) moe_in = o @ Wo^T + bo                        [256,768]
    gemm_kernel<64, 64, 4, 4, true><<<dim3(12, 4, 1), 256>>>(
        nullptr, OFF_O, Cx, 0,  Wo, 0, Cx, 0,  bo, 0, 0, 1,
        nullptr, OFF_MOEIN, Cx, 0,  Bx, Cx, Cx);

    // 6) attr_in + gate top-3 weights + router scores
    attr_build_kernel<<<Bx * Ax, 256>>>(
        prompt, visual_cls, gate_w, gate_b, r1_w, r1_b, r2_w, r2_b);

    // 7) eo[b,a,e,:] = attr @ exp_w[e]^T + exp_b[e]    dominant GEMM, batched E
    gemm_kernel<128, 128, 8, 8, true><<<dim3(6, 20, Ex), 256>>>(
        nullptr, OFF_ATTR, Cx, 0,  exp_w, 0, Cx, (long)Cx * Cx,  exp_b, 0, Cx, 1,
        nullptr, OFF_EO, Ex * Cx, (long)Cx,  Bx * Ax, Cx, Cx);

    // 8) top-7 attribute softmax * gate weights -> output
    final_kernel<<<Bx, 256>>>(out);
}

// round 3
// speedup vs baseline: 1.6043x; 1.6043x over previous
#include <cuda_runtime.h>
#include <math.h>
#include <stdint.h>

// ---------------------------------------------------------------------------
// CLIP_SVPR_ReID fused head — R3: all GEMMs on tensor cores (mma.sync tf32).
//   - single-query cross attention folded to qhat/ctx form
//   - router collapsed to a scalar score
//   - tf32 m16n8k8 mma GEMM template with register-prefetch double buffering
// kernel_launch contains ONLY kernel launches (no runtime API calls).
// ---------------------------------------------------------------------------

namespace {
constexpr int Bx = 256;   // batch
constexpr int Nx = 256;   // patches
constexpr int Cx = 768;   // channels
constexpr int Ax = 10;    // attributes
constexpr int Hx = 8;     // heads
constexpr int Ex = 4;     // experts
constexpr int Dx = 96;    // head dim
constexpr float SCALE = 0.1020620726159657f; // 96^-0.5

constexpr long OFF_Q     = 0;                                 // [B,C]
constexpr long OFF_QHAT  = OFF_Q     + (long)Bx * Cx;         // [B,H,C]
constexpr long OFF_CTX   = OFF_QHAT  + (long)Bx * Hx * Cx;    // [B,H,C]
constexpr long OFF_O     = OFF_CTX   + (long)Bx * Hx * Cx;    // [B,C]
constexpr long OFF_MOEIN = OFF_O     + (long)Bx * Cx;         // [B,C]
constexpr long OFF_ATTR  = OFF_MOEIN + (long)Bx * Cx;         // [B*A,C]
constexpr long OFF_GATEW = OFF_ATTR  + (long)Bx * Ax * Cx;    // [B*A,E]
constexpr long OFF_SCORE = OFF_GATEW + (long)Bx * Ax * Ex;    // [B*A]
constexpr long OFF_EO    = OFF_SCORE + (long)Bx * Ax;         // [B*A, E*C]
constexpr long SCRATCH_TOTAL = OFF_EO + (long)Bx * Ax * Ex * Cx;
} // namespace

__device__ float g_scratch[SCRATCH_TOTAL];

__device__ __forceinline__ const float* rsv(const float* p, long base) {
    return p ? p : (const float*)g_scratch + base;
}
__device__ __forceinline__ float* rsvw(float* p, long base) {
    return p ? p : (float*)g_scratch + base;
}

__device__ __forceinline__ uint32_t f2tf(float f) {
    uint32_t u;
    asm("cvt.rna.tf32.f32 %0, %1;" : "=r"(u) : "f"(f));
    return u;
}

__device__ __forceinline__ void mma_tf32(float* d, const uint32_t* a, const uint32_t* b) {
    asm volatile(
        "mma.sync.aligned.m16n8k8.row.col.f32.tf32.tf32.f32 "
        "{%0,%1,%2,%3}, {%4,%5,%6,%7}, {%8,%9}, {%0,%1,%2,%3};\n"
        : "+f"(d[0]), "+f"(d[1]), "+f"(d[2]), "+f"(d[3])
        : "r"(a[0]), "r"(a[1]), "r"(a[2]), "r"(a[3]), "r"(b[0]), "r"(b[1]));
}

// ---------------------------------------------------------------------------
// tf32 tensor-core GEMM: C[m,n] = sum_k A[m,k]*B'[k,n] (+ bias[n])
//   BNN=false: B is [N,K] row-major (torch Linear "NT")
//   BNN=true : B is [K,N] row-major ("NN")
// 256 threads = 8 warps (2 x 4); warp tile (BM/2) x (BN/4); BK=16.
// Exact tiling required: M%BM==0, N%BN==0, K%16==0 (true for all call sites).
// Register-prefetch double buffering over the K loop.
// Null A/C pointer + base => operand in g_scratch at that offset.
// ---------------------------------------------------------------------------
template <int BM, int BN, bool BNN>
__global__ __launch_bounds__(256) void mma_gemm(
    const float* __restrict__ Ain, long aBase, int lda, long aOff,
    const float* __restrict__ Bin, int ldb, long bOff,
    const float* __restrict__ biasin, int biasOff, int hasBias,
    float* __restrict__ Cin, long cBase, int ldc, long cOff,
    int K)
{
    constexpr int BK = 16;
    constexpr int BKP = 20;            // pad -> conflict-free fragment LDS
    constexpr int WM = BM / 2;
    constexpr int WN = BN / 4;
    constexpr int MS = WM / 16;
    constexpr int NS = WN / 8;

    __shared__ __align__(16) uint32_t As[BM][BKP];
    __shared__ __align__(16) uint32_t Bs[BN][BKP];

    const int z = blockIdx.z;
    const float* Ap = rsv(Ain, aBase) + (long)z * aOff;
    const float* Bp = Bin + (long)z * bOff;
    const float* biasp = hasBias ? (biasin + (long)z * biasOff) : nullptr;
    float* Cp = rsvw(Cin, cBase) + (long)z * cOff;

    const int tid  = threadIdx.x;
    const int lane = tid & 31;
    const int wid  = tid >> 5;
    const int wm   = wid & 1;
    const int wn   = wid >> 1;
    const int gid  = lane >> 2;        // 0..7
    const int tig  = lane & 3;         // 0..3
    const int m0 = blockIdx.y * BM;
    const int n0 = blockIdx.x * BN;

    float acc[MS][NS][4];
#pragma unroll
    for (int i = 0; i < MS; i++)
#pragma unroll
        for (int j = 0; j < NS; j++)
#pragma unroll
            for (int q = 0; q < 4; q++) acc[i][j][q] = 0.f;

    // ---- loaders (gmem -> prefetch regs -> smem tf32) ----
    constexpr int ASLOT = BM * (BK / 4);             // float4 slots
    constexpr int AIT   = (ASLOT + 255) / 256;
    constexpr bool APRED = (ASLOT % 256) != 0;
    constexpr int BSLOT = BNN ? (BK * (BN / 4)) : (BN * (BK / 4));
    constexpr int BIT   = (BSLOT + 255) / 256;
    constexpr bool BPRED = (BSLOT % 256) != 0;

    float4 pa[AIT], pb[BIT];

    auto loadA = [&](int k0) {
#pragma unroll
        for (int i = 0; i < AIT; i++) {
            int idx = tid + i * 256;
            if (!APRED || idx < ASLOT)
                pa[i] = *reinterpret_cast<const float4*>(
                    Ap + (long)(m0 + (idx >> 2)) * lda + k0 + (idx & 3) * 4);
        }
    };
    auto storeA = [&]() {
#pragma unroll
        for (int i = 0; i < AIT; i++) {
            int idx = tid + i * 256;
            if (!APRED || idx < ASLOT) {
                int r = idx >> 2, kq = (idx & 3) * 4;
                *reinterpret_cast<uint4*>(&As[r][kq]) =
                    make_uint4(f2tf(pa[i].x), f2tf(pa[i].y), f2tf(pa[i].z), f2tf(pa[i].w));
            }
        }
    };
    auto loadB = [&](int k0) {
#pragma unroll
        for (int i = 0; i < BIT; i++) {
            int idx = tid + i * 256;
            if (!BPRED || idx < BSLOT) {
                if (BNN) {
                    int kr = idx / (BN / 4), nq = (idx % (BN / 4)) * 4;
                    pb[i] = *reinterpret_cast<const float4*>(
                        Bp + (long)(k0 + kr) * ldb + n0 + nq);
                } else {
                    pb[i] = *reinterpret_cast<const float4*>(
                        Bp + (long)(n0 + (idx >> 2)) * ldb + k0 + (idx & 3) * 4);
                }
            }
        }
    };
    auto storeB = [&]() {
#pragma unroll
        for (int i = 0; i < BIT; i++) {
            int idx = tid + i * 256;
            if (!BPRED || idx < BSLOT) {
                if (BNN) {
                    int kr = idx / (BN / 4), nq = (idx % (BN / 4)) * 4;
                    Bs[nq + 0][kr] = f2tf(pb[i].x);
                    Bs[nq + 1][kr] = f2tf(pb[i].y);
                    Bs[nq + 2][kr] = f2tf(pb[i].z);
                    Bs[nq + 3][kr] = f2tf(pb[i].w);
                } else {
                    int r = idx >> 2, kq = (idx & 3) * 4;
                    *reinterpret_cast<uint4*>(&Bs[r][kq]) =
                        make_uint4(f2tf(pb[i].x), f2tf(pb[i].y), f2tf(pb[i].z), f2tf(pb[i].w));
                }
            }
        }
    };

    loadA(0); loadB(0);
    for (int k0 = 0; k0 < K; k0 += BK) {
        storeA(); storeB();
        __syncthreads();
        if (k0 + BK < K) { loadA(k0 + BK); loadB(k0 + BK); }
#pragma unroll
        for (int k8 = 0; k8 < 2; k8++) {
            uint32_t af[MS][4], bf[NS][2];
#pragma unroll
            for (int im = 0; im < MS; im++) {
                int row = wm * WM + im * 16;
                af[im][0] = As[row + gid    ][k8 * 8 + tig];
                af[im][1] = As[row + gid + 8][k8 * 8 + tig];
                af[im][2] = As[row + gid    ][k8 * 8 + tig + 4];
                af[im][3] = As[row + gid + 8][k8 * 8 + tig + 4];
            }
#pragma unroll
            for (int jn = 0; jn < NS; jn++) {
                int col = wn * WN + jn * 8;
                bf[jn][0] = Bs[col + gid][k8 * 8 + tig];
                bf[jn][1] = Bs[col + gid][k8 * 8 + tig + 4];
            }
#pragma unroll
            for (int im = 0; im < MS; im++)
#pragma unroll
                for (int jn = 0; jn < NS; jn++)
                    mma_tf32(acc[im][jn], af[im], bf[jn]);
        }
        __syncthreads();
    }

    // epilogue: c0,c1 -> (row gid, cols 2*tig, 2*tig+1); c2,c3 -> row gid+8
#pragma unroll
    for (int im = 0; im < MS; im++) {
#pragma unroll
        for (int jn = 0; jn < NS; jn++) {
            int row = m0 + wm * WM + im * 16 + gid;
            int col = n0 + wn * WN + jn * 8 + 2 * tig;
            float b0 = biasp ? biasp[col] : 0.f;
            float b1 = biasp ? biasp[col + 1] : 0.f;
            Cp[(long)row * ldc + col]           = acc[im][jn][0] + b0;
            Cp[(long)row * ldc + col + 1]       = acc[im][jn][1] + b1;
            Cp[(long)(row + 8) * ldc + col]     = acc[im][jn][2] + b0;
            Cp[(long)(row + 8) * ldc + col + 1] = acc[im][jn][3] + b1;
        }
    }
}

// ---------------------------------------------------------------------------
// Fused attention for the single query token. One CTA per batch element.
// ---------------------------------------------------------------------------
__global__ __launch_bounds__(256) void attn_kernel(const float* __restrict__ x)
{
    __shared__ float qs[Hx * Cx];   // 24 KB
    __shared__ float att[Hx * Nx];  // 8 KB
    const float* qhat = (const float*)g_scratch + OFF_QHAT;
    float* ctx = (float*)g_scratch + OFF_CTX;
    const int b = blockIdx.x;
    const int t = threadIdx.x;
    const int warp = t >> 5, lane = t & 31;
    const float* xb = x + (long)b * Nx * Cx;

    for (int i = t; i < Hx * Cx; i += 256) qs[i] = qhat[(long)b * Hx * Cx + i];
    __syncthreads();

    for (int n = warp; n < Nx; n += 8) {
        const float* xr = xb + (long)n * Cx;
        float acc[Hx];
#pragma unroll
        for (int h = 0; h < Hx; h++) acc[h] = 0.f;
        for (int c = lane; c < Cx; c += 32) {
            float xv = xr[c];
#pragma unroll
            for (int h = 0; h < Hx; h++) acc[h] += xv * qs[h * Cx + c];
        }
#pragma unroll
        for (int h = 0; h < Hx; h++) {
#pragma unroll
            for (int o = 16; o; o >>= 1)
                acc[h] += __shfl_xor_sync(0xffffffffu, acc[h], o);
        }
        if (lane == 0) {
#pragma unroll
            for (int h = 0; h < Hx; h++) att[h * Nx + n] = acc[h] * SCALE;
        }
    }
    __syncthreads();

    {
        const int h = warp;
        float v[Nx / 32];
        float mx = -3.4e38f;
#pragma unroll
        for (int i = 0; i < Nx / 32; i++) {
            v[i] = att[h * Nx + lane + 32 * i];
            mx = fmaxf(mx, v[i]);
        }
#pragma unroll
        for (int o = 16; o; o >>= 1)
            mx = fmaxf(mx, __shfl_xor_sync(0xffffffffu, mx, o));
        float s = 0.f;
#pragma unroll
        for (int i = 0; i < Nx / 32; i++) { v[i] = __expf(v[i] - mx); s += v[i]; }
#pragma unroll
        for (int o = 16; o; o >>= 1)
            s += __shfl_xor_sync(0xffffffffu, s, o);
        float inv = 1.f / s;
#pragma unroll
        for (int i = 0; i < Nx / 32; i++) att[h * Nx + lane + 32 * i] = v[i] * inv;
    }
    __syncthreads();

    float a0[Hx], a1[Hx], a2[Hx];
#pragma unroll
    for (int h = 0; h < Hx; h++) { a0[h] = 0.f; a1[h] = 0.f; a2[h] = 0.f; }
    for (int n = 0; n < Nx; n++) {
        const float* xr = xb + (long)n * Cx;
        float x0 = xr[t], x1 = xr[t + 256], x2 = xr[t + 512];
#pragma unroll
        for (int h = 0; h < Hx; h++) {
            float w = att[h * Nx + n];
            a0[h] += w * x0; a1[h] += w * x1; a2[h] += w * x2;
        }
    }
#pragma unroll
    for (int h = 0; h < Hx; h++) {
        float* cb = ctx + (long)b * Hx * Cx + h * Cx;
        cb[t] = a0[h]; cb[t + 256] = a1[h]; cb[t + 512] = a2[h];
    }
}

// ---------------------------------------------------------------------------
// attr_in build + gate top-3 softmax weights + router score. CTA per (b,a).
// ---------------------------------------------------------------------------
__device__ __forceinline__ float gelu_tanh(float v) {
    return 0.5f * v * (1.f + tanhf(0.7978845608028654f * (v + 0.044715f * v * v * v)));
}

__global__ __launch_bounds__(256) void attr_build_kernel(
    const float* __restrict__ prompt, const float* __restrict__ vcls,
    const float* __restrict__ gate_w, const float* __restrict__ gate_b,
    const float* __restrict__ r1_w, const float* __restrict__ r1_b,
    const float* __restrict__ r2_w, const float* __restrict__ r2_b)
{
    const float* moein = (const float*)g_scratch + OFF_MOEIN;
    float* attr  = (float*)g_scratch + OFF_ATTR;
    float* gatew = (float*)g_scratch + OFF_GATEW;
    float* scores = (float*)g_scratch + OFF_SCORE;

    const int row = blockIdx.x;
    const int b = row / Ax, a = row % Ax;
    const int t = threadIdx.x;
    float p[7] = {0, 0, 0, 0, 0, 0, 0};
    for (int c = t; c < Cx; c += 256) {
        float v = moein[(long)b * Cx + c] + prompt[a * Cx + c] + vcls[(long)b * Cx + c];
        attr[(long)row * Cx + c] = v;
        p[0] += v * gate_w[0 * Cx + c];
        p[1] += v * gate_w[1 * Cx + c];
        p[2] += v * gate_w[2 * Cx + c];
        p[3] += v * gate_w[3 * Cx + c];
        p[4] += v * r1_w[c];
        p[5] += r2_w[c];
        p[6] += r2_b[c];
    }
#pragma unroll
    for (int i = 0; i < 7; i++)
#pragma unroll
        for (int o = 16; o; o >>= 1)
            p[i] += __shfl_xor_sync(0xffffffffu, p[i], o);

    __shared__ float red[8][7];
    const int warp = t >> 5, lane = t & 31;
    if (lane == 0)
        for (int i = 0; i < 7; i++) red[warp][i] = p[i];
    __syncthreads();

    if (t == 0) {
        float s[7];
        for (int i = 0; i < 7; i++) {
            s[i] = 0.f;
            for (int w = 0; w < 8; w++) s[i] += red[w][i];
        }
        float g[4];
        for (int e = 0; e < 4; e++) g[e] = s[e] + gate_b[e];
        float srt[4] = {g[0], g[1], g[2], g[3]};
        for (int i = 0; i < 3; i++)
            for (int j = 0; j < 3 - i; j++)
                if (srt[j] < srt[j + 1]) { float tm = srt[j]; srt[j] = srt[j + 1]; srt[j + 1] = tm; }
        float thr = srt[2], mx = srt[0];
        float w[4], ws = 0.f;
        for (int e = 0; e < 4; e++) {
            if (g[e] >= thr) { w[e] = __expf(g[e] - mx); ws += w[e]; }
            else w[e] = 0.f;
        }
        float inv = 1.f / ws;
        for (int e = 0; e < 4; e++) gatew[(long)row * 4 + e] = w[e] * inv;

        float hsc = gelu_tanh(s[4] + r1_b[0]);
        scores[row] = hsc * (s[5] * (1.f / 768.f)) + s[6] * (1.f / 768.f);
    }
}

// ---------------------------------------------------------------------------
// Final combine. One CTA per batch element.
// ---------------------------------------------------------------------------
__global__ __launch_bounds__(256) void final_kernel(float* __restrict__ out)
{
    const float* eo = (const float*)g_scratch + OFF_EO;
    const float* gatew = (const float*)g_scratch + OFF_GATEW;
    const float* scores = (const float*)g_scratch + OFF_SCORE;

    const int b = blockIdx.x, t = threadIdx.x;
    __shared__ float coef[Ax * Ex];
    __shared__ float sc[Ax];
    if (t < Ax) sc[t] = scores[b * Ax + t];
    __syncthreads();
    if (t == 0) {
        float mx = sc[0];
        for (int a = 1; a < Ax; a++) mx = fmaxf(mx, sc[a]);
        float wt[Ax];
        float ssum = 0.f;
        for (int a = 0; a < Ax; a++) {
            int rank = 0;
            for (int a2 = 0; a2 < Ax; a2++)
                if (sc[a2] > sc[a] || (sc[a2] == sc[a] && a2 < a)) rank++;
            if (rank < 7) { wt[a] = __expf(sc[a] - mx); ssum += wt[a]; }
            else wt[a] = 0.f;
        }
        float inv = 1.f / ssum;
        for (int a = 0; a < Ax; a++) {
            float w = wt[a] * inv;
            for (int e = 0; e < Ex; e++)
                coef[a * Ex + e] = w * gatew[(long)(b * Ax + a) * Ex + e];
        }
    }
    __syncthreads();
    float cf[Ax * Ex];
#pragma unroll
    for (int i = 0; i < Ax * Ex; i++) cf[i] = coef[i];
    const float* eb = eo + (long)b * Ax * Ex * Cx;
    for (int c = t; c < Cx; c += 256) {
        float acc = 0.f;
#pragma unroll
        for (int a = 0; a < Ax; a++)
#pragma unroll
            for (int e = 0; e < Ex; e++)
                acc += cf[a * Ex + e] * eb[(long)a * Ex * Cx + e * Cx + c];
        out[(long)b * Cx + c] = acc;
    }
}

// ---------------------------------------------------------------------------
// Launcher — kernel launches ONLY.
// ---------------------------------------------------------------------------
extern "C" void kernel_launch(void* const* d_in, const int* in_sizes, int n_in,
                              void* d_out, int out_size)
{
    (void)in_sizes; (void)n_in; (void)out_size;
    const float* text_cls   = (const float*)d_in[0];
    const float* visual_cls = (const float*)d_in[1];
    const float* x          = (const float*)d_in[2];
    const float* prompt     = (const float*)d_in[3];
    const float* Wq  = (const float*)d_in[4];
    const float* bq  = (const float*)d_in[5];
    const float* Wk  = (const float*)d_in[6];
    // d_in[7] = bk: cancels in softmax
    const float* Wv  = (const float*)d_in[8];
    const float* bv  = (const float*)d_in[9];
    const float* Wo  = (const float*)d_in[10];
    const float* bo  = (const float*)d_in[11];
    const float* gate_w = (const float*)d_in[12];
    const float* gate_b = (const float*)d_in[13];
    const float* exp_w  = (const float*)d_in[14];
    const float* exp_b  = (const float*)d_in[15];
    const float* r1_w   = (const float*)d_in[16];
    const float* r1_b   = (const float*)d_in[17];
    const float* r2_w   = (const float*)d_in[18];
    const float* r2_b   = (const float*)d_in[19];
    float* out = (float*)d_out;

    // 1) q = text_cls @ Wq^T + bq        M=256,N=768,K=768 (NT)
    mma_gemm<64, 64, false><<<dim3(12, 4, 1), 256>>>(
        text_cls, 0, Cx, 0,  Wq, Cx, 0,  bq, 0, 1,
        nullptr, OFF_Q, Cx, 0,  Cx);

    // 2) qhat[b,h,:] = q[b,h-slice] @ Wk[h-rows]   M=256,N=768,K=96 (NN), z=h
    mma_gemm<64, 64, true><<<dim3(12, 4, Hx), 256>>>(
        nullptr, OFF_Q, Cx, Dx,  Wk, Cx, (long)Dx * Cx,  nullptr, 0, 0,
        nullptr, OFF_QHAT, Hx * Cx, Cx,  Dx);

    // 3) fused logits + softmax + ctx
    attn_kernel<<<Bx, 256>>>(x);

    // 4) o[b, h*96+d] = ctx[b,h] @ Wv_h^T + bv     M=256,N=96,K=768 (NT), z=h
    mma_gemm<64, 32, false><<<dim3(3, 4, Hx), 256>>>(
        nullptr, OFF_CTX, Hx * Cx, Cx,  Wv, Cx, (long)Dx * Cx,  bv, Dx, 1,
        nullptr, OFF_O, Cx, Dx,  Cx);

    // 5) moe_in = o @ Wo^T + bo          M=256,N=768,K=768 (NT)
    mma_gemm<64, 64, false><<<dim3(12, 4, 1), 256>>>(
        nullptr, OFF_O, Cx, 0,  Wo, Cx, 0,  bo, 0, 1,
        nullptr, OFF_MOEIN, Cx, 0,  Cx);

    // 6) attr_in + gate weights + router scores
    attr_build_kernel<<<Bx * Ax, 256>>>(
        prompt, visual_cls, gate_w, gate_b, r1_w, r1_b, r2_w, r2_b);

    // 7) eo = attr @ exp_w[e]^T + exp_b[e]   M=2560,N=768,K=768 (NT), z=e
    mma_gemm<128, 128, false><<<dim3(6, 20, Ex), 256>>>(
        nullptr, OFF_ATTR, Cx, 0,  exp_w, Cx, (long)Cx * Cx,  exp_b, Cx, 1,
        nullptr, OFF_EO, Ex * Cx, Cx,  Cx);

    // 8) top-7 attribute softmax * gate weights -> output
    final_kernel<<<Bx, 256>>>(out);
}